// round 2
// baseline (speedup 1.0000x reference)
#include <cuda_runtime.h>
#include <cstdint>

// Problem constants (fixed by the reference)
#define NN 50000      // nodes
#define NE 1250000    // edges
#define DN 64         // node feat
#define DE 16         // edge feat
#define DH 64         // hidden

// ---------------------------------------------------------------------------
// Scratch (device globals; no allocation allowed)
// ---------------------------------------------------------------------------
__device__ float g_srcpart[NN * DH];   // node_features @ W_m1[0:64]
__device__ float g_hsum[NN * DH];      // segment-sum of relu hidden
__device__ float g_T[NN * DH];         // intermediate of update MLP
__device__ int   g_deg[NN];            // in-degree per node
__device__ float g_Wc[DH * DH];        // W_m2 @ W_u1[64:128]
__device__ float g_bc[DH];             // b_m2 @ W_u1[64:128]

// ---------------------------------------------------------------------------
// Zero the accumulators (graph-capturable kernel, no memset API)
// ---------------------------------------------------------------------------
__global__ void zero_kernel() {
    int idx = blockIdx.x * blockDim.x + threadIdx.x;
    if (idx < NN * DH / 4)
        reinterpret_cast<float4*>(g_hsum)[idx] = make_float4(0.f, 0.f, 0.f, 0.f);
    if (idx < NN)
        g_deg[idx] = 0;
}

// ---------------------------------------------------------------------------
// Precompute folded weights: Wc = w_m2 @ w_u1[64:128], bc = b_m2 @ w_u1[64:128]
// ---------------------------------------------------------------------------
__global__ void prep_kernel(const float* __restrict__ w_m2,
                            const float* __restrict__ b_m2,
                            const float* __restrict__ w_u1) {
    int tid = blockIdx.x * blockDim.x + threadIdx.x;
    int stride = gridDim.x * blockDim.x;
    for (int idx = tid; idx < DH * DH; idx += stride) {
        int k = idx >> 6, j = idx & 63;
        float s = 0.f;
        #pragma unroll 8
        for (int m = 0; m < DH; m++)
            s += w_m2[k * DH + m] * w_u1[(DN + m) * DH + j];
        g_Wc[idx] = s;
    }
    if (tid < DH) {
        float s = 0.f;
        #pragma unroll 8
        for (int m = 0; m < DH; m++)
            s += b_m2[m] * w_u1[(DN + m) * DH + tid];
        g_bc[tid] = s;
    }
}

// ---------------------------------------------------------------------------
// Generic [M x 64] = A[M x 64] @ W[64 x 64] (+ bias). 128-row tiles,
// 256 threads, 8x4 register tile per thread. W read through L1 as float4.
// ---------------------------------------------------------------------------
__global__ void gemm_k64_kernel(const float* __restrict__ A,
                                const float* __restrict__ W,
                                const float* __restrict__ bias,
                                float* __restrict__ C, int M) {
    __shared__ float As[128 * 66];   // pad 66 -> conflict-free 8-row strides
    const int row0 = blockIdx.x * 128;
    const int tid = threadIdx.x;

    for (int idx = tid; idx < 128 * 64; idx += 256) {
        int r = idx >> 6, k = idx & 63;
        int row = row0 + r;
        As[r * 66 + k] = (row < M) ? A[(size_t)row * 64 + k] : 0.f;
    }
    __syncthreads();

    const int tc = tid & 15, tr = tid >> 4;
    const int j0 = tc * 4, r0 = tr * 8;
    float4 acc[8];
    #pragma unroll
    for (int i = 0; i < 8; i++) acc[i] = make_float4(0.f, 0.f, 0.f, 0.f);

    #pragma unroll 8
    for (int k = 0; k < 64; k++) {
        float4 w = *reinterpret_cast<const float4*>(&W[k * 64 + j0]);
        #pragma unroll
        for (int i = 0; i < 8; i++) {
            float a = As[(r0 + i) * 66 + k];
            acc[i].x += a * w.x; acc[i].y += a * w.y;
            acc[i].z += a * w.z; acc[i].w += a * w.w;
        }
    }

    float4 b = make_float4(0.f, 0.f, 0.f, 0.f);
    if (bias) b = *reinterpret_cast<const float4*>(&bias[j0]);

    #pragma unroll
    for (int i = 0; i < 8; i++) {
        int row = row0 + r0 + i;
        if (row < M) {
            float4 v;
            v.x = acc[i].x + b.x; v.y = acc[i].y + b.y;
            v.z = acc[i].z + b.z; v.w = acc[i].w + b.w;
            *reinterpret_cast<float4*>(&C[(size_t)row * 64 + j0]) = v;
        }
    }
}

// ---------------------------------------------------------------------------
// Edge kernel: per 128-edge tile, EP = E_tile @ w_m1[64:80]; then
// h = relu(srcpart[src] + EP + b_m1); vector-red into g_hsum[dst]; deg++.
// ---------------------------------------------------------------------------
__global__ void edge_kernel(const float* __restrict__ ef,
                            const int* __restrict__ eidx,
                            const float* __restrict__ w_m1,
                            const float* __restrict__ b_m1) {
    __shared__ float Es[128 * 17];
    __shared__ int s_sh[128];
    __shared__ int d_sh[128];
    const int e0 = blockIdx.x * 128;
    const int tid = threadIdx.x;

    if (tid < 128) {
        int e = e0 + tid;
        int s = 0, d = 0;
        if (e < NE) {
            s = eidx[e];
            d = eidx[NE + e];
            atomicAdd(&g_deg[d], 1);
        }
        s_sh[tid] = s;
        d_sh[tid] = d;
    }
    for (int idx = tid; idx < 128 * 16; idx += 256) {
        int r = idx >> 4, k = idx & 15;
        int e = e0 + r;
        Es[r * 17 + k] = (e < NE) ? ef[(size_t)e * 16 + k] : 0.f;
    }
    __syncthreads();

    const int tc = tid & 15, tr = tid >> 4;
    const int j0 = tc * 4, r0 = tr * 8;
    float4 acc[8];
    #pragma unroll
    for (int i = 0; i < 8; i++) acc[i] = make_float4(0.f, 0.f, 0.f, 0.f);

    #pragma unroll
    for (int k = 0; k < 16; k++) {
        float4 w = *reinterpret_cast<const float4*>(&w_m1[(DN + k) * 64 + j0]);
        #pragma unroll
        for (int i = 0; i < 8; i++) {
            float a = Es[(r0 + i) * 17 + k];
            acc[i].x += a * w.x; acc[i].y += a * w.y;
            acc[i].z += a * w.z; acc[i].w += a * w.w;
        }
    }

    float4 b = *reinterpret_cast<const float4*>(&b_m1[j0]);

    #pragma unroll
    for (int i = 0; i < 8; i++) {
        int el = r0 + i;
        int e = e0 + el;
        if (e < NE) {
            const float4 sp = *reinterpret_cast<const float4*>(
                &g_srcpart[(size_t)s_sh[el] * 64 + j0]);
            float hx = fmaxf(acc[i].x + sp.x + b.x, 0.f);
            float hy = fmaxf(acc[i].y + sp.y + b.y, 0.f);
            float hz = fmaxf(acc[i].z + sp.z + b.z, 0.f);
            float hw = fmaxf(acc[i].w + sp.w + b.w, 0.f);
            float* p = &g_hsum[(size_t)d_sh[el] * 64 + j0];
            asm volatile("red.global.add.v4.f32 [%0], {%1, %2, %3, %4};"
                         :: "l"(p), "f"(hx), "f"(hy), "f"(hz), "f"(hw)
                         : "memory");
        }
    }
}

// ---------------------------------------------------------------------------
// Node update part 1: T = relu(X @ w_u1[0:64] + Hsum @ Wc + deg*bc + b_u1)
// ---------------------------------------------------------------------------
__global__ void nodeT_kernel(const float* __restrict__ X,
                             const float* __restrict__ w_u1,
                             const float* __restrict__ b_u1) {
    __shared__ float As[128 * 66];
    const int row0 = blockIdx.x * 128;
    const int tid = threadIdx.x;
    const int tc = tid & 15, tr = tid >> 4;
    const int j0 = tc * 4, r0 = tr * 8;

    float4 acc[8];
    #pragma unroll
    for (int i = 0; i < 8; i++) acc[i] = make_float4(0.f, 0.f, 0.f, 0.f);

    // pass 1: X @ w_u1[0:64]
    for (int idx = tid; idx < 128 * 64; idx += 256) {
        int r = idx >> 6, k = idx & 63;
        int row = row0 + r;
        As[r * 66 + k] = (row < NN) ? X[(size_t)row * 64 + k] : 0.f;
    }
    __syncthreads();
    #pragma unroll 8
    for (int k = 0; k < 64; k++) {
        float4 w = *reinterpret_cast<const float4*>(&w_u1[k * 64 + j0]);
        #pragma unroll
        for (int i = 0; i < 8; i++) {
            float a = As[(r0 + i) * 66 + k];
            acc[i].x += a * w.x; acc[i].y += a * w.y;
            acc[i].z += a * w.z; acc[i].w += a * w.w;
        }
    }
    __syncthreads();

    // pass 2: Hsum @ Wc
    for (int idx = tid; idx < 128 * 64; idx += 256) {
        int r = idx >> 6, k = idx & 63;
        int row = row0 + r;
        As[r * 66 + k] = (row < NN) ? g_hsum[(size_t)row * 64 + k] : 0.f;
    }
    __syncthreads();
    #pragma unroll 8
    for (int k = 0; k < 64; k++) {
        float4 w = *reinterpret_cast<const float4*>(&g_Wc[k * 64 + j0]);
        #pragma unroll
        for (int i = 0; i < 8; i++) {
            float a = As[(r0 + i) * 66 + k];
            acc[i].x += a * w.x; acc[i].y += a * w.y;
            acc[i].z += a * w.z; acc[i].w += a * w.w;
        }
    }

    float4 bc = *reinterpret_cast<const float4*>(&g_bc[j0]);
    float4 bu = *reinterpret_cast<const float4*>(&b_u1[j0]);

    #pragma unroll
    for (int i = 0; i < 8; i++) {
        int row = row0 + r0 + i;
        if (row < NN) {
            float dg = (float)g_deg[row];
            float4 v;
            v.x = fmaxf(acc[i].x + dg * bc.x + bu.x, 0.f);
            v.y = fmaxf(acc[i].y + dg * bc.y + bu.y, 0.f);
            v.z = fmaxf(acc[i].z + dg * bc.z + bu.z, 0.f);
            v.w = fmaxf(acc[i].w + dg * bc.w + bu.w, 0.f);
            *reinterpret_cast<float4*>(&g_T[(size_t)row * 64 + j0]) = v;
        }
    }
}

// ---------------------------------------------------------------------------
// Launch
// ---------------------------------------------------------------------------
extern "C" void kernel_launch(void* const* d_in, const int* in_sizes, int n_in,
                              void* d_out, int out_size) {
    const float* node_f = (const float*)d_in[0];
    const float* edge_f = (const float*)d_in[1];
    const int*   eidx   = (const int*)d_in[2];
    const float* w_m1   = (const float*)d_in[3];
    const float* b_m1   = (const float*)d_in[4];
    const float* w_m2   = (const float*)d_in[5];
    const float* b_m2   = (const float*)d_in[6];
    const float* w_u1   = (const float*)d_in[7];
    const float* b_u1   = (const float*)d_in[8];
    const float* w_u2   = (const float*)d_in[9];
    const float* b_u2   = (const float*)d_in[10];
    float* out = (float*)d_out;

    // resolve scratch symbol addresses (no allocation; capture-safe host calls)
    float *p_srcpart, *p_T;
    cudaGetSymbolAddress((void**)&p_srcpart, g_srcpart);
    cudaGetSymbolAddress((void**)&p_T, g_T);

    const int nodeBlocks = (NN + 127) / 128;   // 391
    const int edgeBlocks = (NE + 127) / 128;   // 9766

    zero_kernel<<<(NN * DH / 4 + 255) / 256, 256>>>();
    prep_kernel<<<16, 256>>>(w_m2, b_m2, w_u1);
    // src_part = node_features @ w_m1[0:64]  (no bias)
    gemm_k64_kernel<<<nodeBlocks, 256>>>(node_f, w_m1, nullptr, p_srcpart, NN);
    // per-edge relu + scatter
    edge_kernel<<<edgeBlocks, 256>>>(edge_f, eidx, w_m1, b_m1);
    // T = relu(X @ Wu1a + Hsum @ Wc + deg*bc + b_u1)
    nodeT_kernel<<<nodeBlocks, 256>>>(node_f, w_u1, b_u1);
    // out = T @ w_u2 + b_u2
    gemm_k64_kernel<<<nodeBlocks, 256>>>(p_T, w_u2, b_u2, out, NN);
}

// round 4
// speedup vs baseline: 1.2197x; 1.2197x over previous
#include <cuda_runtime.h>
#include <cstdint>

#define NN 50000      // nodes
#define NE 1250000    // edges
#define DN 64         // node feat
#define DE 16         // edge feat
#define DH 64         // hidden

// ---------------------------------------------------------------------------
// Scratch (device globals; no allocation allowed)
// ---------------------------------------------------------------------------
__device__ float g_srcpart[NN * DH];   // node_features @ W_m1[0:64]
__device__ float g_hsum[NN * DH];      // segment-sum of relu hidden
__device__ int   g_deg[NN];            // in-degree per node
__device__ float g_Wc[DH * DH];        // W_m2 @ W_u1[64:128]
__device__ float g_bc[DH];             // b_m2 @ W_u1[64:128]

// ---------------------------------------------------------------------------
// init: zero accumulators + precompute folded weights, one kernel.
// Blocks [0, ZB) zero g_hsum/g_deg; block ZB does the 64x64 fold.
// ---------------------------------------------------------------------------
#define ZB 3125   // = NN*DH/4 / 256
__global__ void init_kernel(const float* __restrict__ w_m2,
                            const float* __restrict__ b_m2,
                            const float* __restrict__ w_u1) {
    if (blockIdx.x < ZB) {
        int idx = blockIdx.x * 256 + threadIdx.x;
        reinterpret_cast<float4*>(g_hsum)[idx] = make_float4(0.f, 0.f, 0.f, 0.f);
        if (idx < NN) g_deg[idx] = 0;
    } else {
        int tid = threadIdx.x;
        for (int idx = tid; idx < DH * DH; idx += 256) {
            int k = idx >> 6, j = idx & 63;
            float s = 0.f;
            #pragma unroll 8
            for (int m = 0; m < DH; m++)
                s += w_m2[k * DH + m] * w_u1[(DN + m) * DH + j];
            g_Wc[idx] = s;
        }
        if (tid < DH) {
            float s = 0.f;
            #pragma unroll 8
            for (int m = 0; m < DH; m++)
                s += b_m2[m] * w_u1[(DN + m) * DH + tid];
            g_bc[tid] = s;
        }
    }
}

// ---------------------------------------------------------------------------
// [M x 64] = A[M x 64] @ W[64 x 64] (no bias) -> C.  Used for srcpart.
// ---------------------------------------------------------------------------
__global__ void gemm_k64_kernel(const float* __restrict__ A,
                                const float* __restrict__ W,
                                float* __restrict__ C, int M) {
    __shared__ float As[128 * 66];
    const int row0 = blockIdx.x * 128;
    const int tid = threadIdx.x;

    for (int idx = tid; idx < 128 * 64; idx += 256) {
        int r = idx >> 6, k = idx & 63;
        int row = row0 + r;
        As[r * 66 + k] = (row < M) ? A[(size_t)row * 64 + k] : 0.f;
    }
    __syncthreads();

    const int tc = tid & 15, tr = tid >> 4;
    const int j0 = tc * 4, r0 = tr * 8;
    float4 acc[8];
    #pragma unroll
    for (int i = 0; i < 8; i++) acc[i] = make_float4(0.f, 0.f, 0.f, 0.f);

    #pragma unroll 8
    for (int k = 0; k < 64; k++) {
        float4 w = *reinterpret_cast<const float4*>(&W[k * 64 + j0]);
        #pragma unroll
        for (int i = 0; i < 8; i++) {
            float a = As[(r0 + i) * 66 + k];
            acc[i].x += a * w.x; acc[i].y += a * w.y;
            acc[i].z += a * w.z; acc[i].w += a * w.w;
        }
    }

    #pragma unroll
    for (int i = 0; i < 8; i++) {
        int row = row0 + r0 + i;
        if (row < M)
            *reinterpret_cast<float4*>(&C[(size_t)row * 64 + j0]) = acc[i];
    }
}

// ---------------------------------------------------------------------------
// Edge kernel v2: 64 edges / 256-thread block, 4 edges x 4 cols per thread.
// Smaller reg tile -> 4 blocks/SM (occ 50%) for latency hiding on the
// L2-resident srcpart gather + red.global scatter.
// ---------------------------------------------------------------------------
__global__ void __launch_bounds__(256, 4)
edge_kernel(const float* __restrict__ ef,
            const int* __restrict__ eidx,
            const float* __restrict__ w_m1,
            const float* __restrict__ b_m1) {
    __shared__ float Es[64 * 17];
    __shared__ int s_sh[64];
    __shared__ int d_sh[64];
    const int e0 = blockIdx.x * 64;
    const int tid = threadIdx.x;

    if (tid < 64) {
        int e = e0 + tid;
        int s = 0, d = 0;
        if (e < NE) {
            s = eidx[e];
            d = eidx[NE + e];
            atomicAdd(&g_deg[d], 1);
        }
        s_sh[tid] = s;
        d_sh[tid] = d;
    }
    // 64 edges x 16 feats = 256 float4 loads, exactly one per thread.
    {
        int r = tid >> 2, q = tid & 3;
        int e = e0 + r;
        float4 v = make_float4(0.f, 0.f, 0.f, 0.f);
        if (e < NE)
            v = reinterpret_cast<const float4*>(ef)[(size_t)e * 4 + q];
        Es[r * 17 + q * 4 + 0] = v.x;
        Es[r * 17 + q * 4 + 1] = v.y;
        Es[r * 17 + q * 4 + 2] = v.z;
        Es[r * 17 + q * 4 + 3] = v.w;
    }
    __syncthreads();

    const int tc = tid & 15, tr = tid >> 4;
    const int j0 = tc * 4, r0 = tr * 4;

    // Prefetch the 4 srcpart gathers early (independent L2 hits, MLP=4).
    float4 sp[4];
    #pragma unroll
    for (int i = 0; i < 4; i++) {
        int e = e0 + r0 + i;
        const float* p = &g_srcpart[(size_t)s_sh[r0 + i] * 64 + j0];
        sp[i] = (e < NE) ? *reinterpret_cast<const float4*>(p)
                         : make_float4(0.f, 0.f, 0.f, 0.f);
    }

    float4 acc[4];
    #pragma unroll
    for (int i = 0; i < 4; i++) acc[i] = make_float4(0.f, 0.f, 0.f, 0.f);

    #pragma unroll
    for (int k = 0; k < 16; k++) {
        float4 w = *reinterpret_cast<const float4*>(&w_m1[(DN + k) * 64 + j0]);
        #pragma unroll
        for (int i = 0; i < 4; i++) {
            float a = Es[(r0 + i) * 17 + k];
            acc[i].x += a * w.x; acc[i].y += a * w.y;
            acc[i].z += a * w.z; acc[i].w += a * w.w;
        }
    }

    float4 b = *reinterpret_cast<const float4*>(&b_m1[j0]);

    #pragma unroll
    for (int i = 0; i < 4; i++) {
        int e = e0 + r0 + i;
        if (e < NE) {
            float hx = fmaxf(acc[i].x + sp[i].x + b.x, 0.f);
            float hy = fmaxf(acc[i].y + sp[i].y + b.y, 0.f);
            float hz = fmaxf(acc[i].z + sp[i].z + b.z, 0.f);
            float hw = fmaxf(acc[i].w + sp[i].w + b.w, 0.f);
            float* p = &g_hsum[(size_t)d_sh[r0 + i] * 64 + j0];
            asm volatile("red.global.add.v4.f32 [%0], {%1, %2, %3, %4};"
                         :: "l"(p), "f"(hx), "f"(hy), "f"(hz), "f"(hw)
                         : "memory");
        }
    }
}

// ---------------------------------------------------------------------------
// Fused node update: T = relu(X@Wu1a + Hsum@Wc + deg*bc + b_u1) staged in
// smem, then out = T @ w_u2 + b_u2.  Avoids the g_T DRAM round-trip.
// ---------------------------------------------------------------------------
__global__ void fused_node_kernel(const float* __restrict__ X,
                                  const float* __restrict__ w_u1,
                                  const float* __restrict__ b_u1,
                                  const float* __restrict__ w_u2,
                                  const float* __restrict__ b_u2,
                                  float* __restrict__ out) {
    __shared__ float As[128 * 66];
    const int row0 = blockIdx.x * 128;
    const int tid = threadIdx.x;
    const int tc = tid & 15, tr = tid >> 4;
    const int j0 = tc * 4, r0 = tr * 8;

    float4 acc[8];
    #pragma unroll
    for (int i = 0; i < 8; i++) acc[i] = make_float4(0.f, 0.f, 0.f, 0.f);

    // pass 1: X @ w_u1[0:64]
    for (int idx = tid; idx < 128 * 64; idx += 256) {
        int r = idx >> 6, k = idx & 63;
        int row = row0 + r;
        As[r * 66 + k] = (row < NN) ? X[(size_t)row * 64 + k] : 0.f;
    }
    __syncthreads();
    #pragma unroll 8
    for (int k = 0; k < 64; k++) {
        float4 w = *reinterpret_cast<const float4*>(&w_u1[k * 64 + j0]);
        #pragma unroll
        for (int i = 0; i < 8; i++) {
            float a = As[(r0 + i) * 66 + k];
            acc[i].x += a * w.x; acc[i].y += a * w.y;
            acc[i].z += a * w.z; acc[i].w += a * w.w;
        }
    }
    __syncthreads();

    // pass 2: Hsum @ Wc
    for (int idx = tid; idx < 128 * 64; idx += 256) {
        int r = idx >> 6, k = idx & 63;
        int row = row0 + r;
        As[r * 66 + k] = (row < NN) ? g_hsum[(size_t)row * 64 + k] : 0.f;
    }
    __syncthreads();
    #pragma unroll 8
    for (int k = 0; k < 64; k++) {
        float4 w = *reinterpret_cast<const float4*>(&g_Wc[k * 64 + j0]);
        #pragma unroll
        for (int i = 0; i < 8; i++) {
            float a = As[(r0 + i) * 66 + k];
            acc[i].x += a * w.x; acc[i].y += a * w.y;
            acc[i].z += a * w.z; acc[i].w += a * w.w;
        }
    }
    __syncthreads();

    // T = relu(acc + deg*bc + b_u1) -> stage back into As
    {
        float4 bc = *reinterpret_cast<const float4*>(&g_bc[j0]);
        float4 bu = *reinterpret_cast<const float4*>(&b_u1[j0]);
        #pragma unroll
        for (int i = 0; i < 8; i++) {
            int r = r0 + i;
            int row = row0 + r;
            float dg = (row < NN) ? (float)g_deg[row] : 0.f;
            As[r * 66 + j0 + 0] = fmaxf(acc[i].x + dg * bc.x + bu.x, 0.f);
            As[r * 66 + j0 + 1] = fmaxf(acc[i].y + dg * bc.y + bu.y, 0.f);
            As[r * 66 + j0 + 2] = fmaxf(acc[i].z + dg * bc.z + bu.z, 0.f);
            As[r * 66 + j0 + 3] = fmaxf(acc[i].w + dg * bc.w + bu.w, 0.f);
        }
    }
    __syncthreads();

    // pass 3: out = T @ w_u2 + b_u2
    #pragma unroll
    for (int i = 0; i < 8; i++) acc[i] = make_float4(0.f, 0.f, 0.f, 0.f);
    #pragma unroll 8
    for (int k = 0; k < 64; k++) {
        float4 w = *reinterpret_cast<const float4*>(&w_u2[k * 64 + j0]);
        #pragma unroll
        for (int i = 0; i < 8; i++) {
            float a = As[(r0 + i) * 66 + k];
            acc[i].x += a * w.x; acc[i].y += a * w.y;
            acc[i].z += a * w.z; acc[i].w += a * w.w;
        }
    }

    float4 b2 = *reinterpret_cast<const float4*>(&b_u2[j0]);
    #pragma unroll
    for (int i = 0; i < 8; i++) {
        int row = row0 + r0 + i;
        if (row < NN) {
            float4 v;
            v.x = acc[i].x + b2.x; v.y = acc[i].y + b2.y;
            v.z = acc[i].z + b2.z; v.w = acc[i].w + b2.w;
            *reinterpret_cast<float4*>(&out[(size_t)row * 64 + j0]) = v;
        }
    }
}

// ---------------------------------------------------------------------------
// Launch
// ---------------------------------------------------------------------------
extern "C" void kernel_launch(void* const* d_in, const int* in_sizes, int n_in,
                              void* d_out, int out_size) {
    const float* node_f = (const float*)d_in[0];
    const float* edge_f = (const float*)d_in[1];
    const int*   eidx   = (const int*)d_in[2];
    const float* w_m1   = (const float*)d_in[3];
    const float* b_m1   = (const float*)d_in[4];
    const float* w_m2   = (const float*)d_in[5];
    const float* b_m2   = (const float*)d_in[6];
    const float* w_u1   = (const float*)d_in[7];
    const float* b_u1   = (const float*)d_in[8];
    const float* w_u2   = (const float*)d_in[9];
    const float* b_u2   = (const float*)d_in[10];
    float* out = (float*)d_out;

    float* p_srcpart;
    cudaGetSymbolAddress((void**)&p_srcpart, g_srcpart);

    const int nodeBlocks = (NN + 127) / 128;   // 391
    const int edgeBlocks = (NE + 63) / 64;     // 19532

    init_kernel<<<ZB + 1, 256>>>(w_m2, b_m2, w_u1);
    gemm_k64_kernel<<<nodeBlocks, 256>>>(node_f, w_m1, p_srcpart, NN);
    edge_kernel<<<edgeBlocks, 256>>>(edge_f, eidx, w_m1, b_m1);
    fused_node_kernel<<<nodeBlocks, 256>>>(node_f, w_u1, b_u1, w_u2, b_u2, out);
}